// round 1
// baseline (speedup 1.0000x reference)
#include <cuda_runtime.h>
#include <cuda_bf16.h>
#include <math.h>

#define NN 20000      // nodes
#define NE 320000     // edges
#define DI 128        // d_in
#define KH 8          // heads
#define HD 64         // head dim

// ---------------- scratch (device globals: allocation-free) ----------------
__device__ __align__(16) float g_mean[(size_t)NE * DI];   // 163.84 MB
__device__ __align__(16) float g_ex[(size_t)NE * KH];     // 10.24 MB
__device__ __align__(16) float g_er[NN * KH];
__device__ __align__(16) float g_V[KH * DI];              // V[k*128+d]
__device__ __align__(16) float g_agg[(size_t)NN * KH * DI]; // 81.92 MB
__device__ int g_deg[NN];
__device__ int g_off[NN + 1];
__device__ int g_cursor[NN];
__device__ int g_order[NE];

// ---------------- k_zero: clear degree histogram ----------------
__global__ void k_zero() {
    int i = blockIdx.x * blockDim.x + threadIdx.x;
    if (i < NN) g_deg[i] = 0;
}

// ---------------- k_v: V[k][d] = sum_h W_enc[d, k*64+h] * attn_l[k,h] ----------------
__global__ void k_v(const float* __restrict__ W_enc, const float* __restrict__ attn_l) {
    __shared__ float al[KH * HD];
    int t = threadIdx.x;
    al[t] = attn_l[t];
    al[t + 256] = attn_l[t + 256];
    __syncthreads();
    for (int o = t; o < KH * DI; o += 256) {
        int k = o >> 7, d = o & 127;
        float s = 0.f;
        #pragma unroll 8
        for (int h = 0; h < HD; h++)
            s += W_enc[d * (KH * HD) + k * HD + h] * al[k * HD + h];
        g_V[o] = s;
    }
}

// ---------------- k_er: er[n,k] = node_feat[n,:] . W_r[k,:]  (one warp / node) ----------------
__global__ void k_er(const float* __restrict__ node_feat, const float* __restrict__ W_r) {
    __shared__ float4 Ws[KH * 32];  // [k][d/4]
    int t = threadIdx.x;
    Ws[t] = ((const float4*)W_r)[t];
    __syncthreads();
    int w = (blockIdx.x * blockDim.x + t) >> 5;
    int lane = t & 31;
    if (w >= NN) return;
    float4 x = ((const float4*)node_feat)[(size_t)w * 32 + lane];
    float p[KH];
    #pragma unroll
    for (int k = 0; k < KH; k++) {
        float4 v = Ws[k * 32 + lane];
        p[k] = x.x * v.x + x.y * v.y + x.z * v.z + x.w * v.w;
    }
    #pragma unroll
    for (int o = 16; o; o >>= 1)
        #pragma unroll
        for (int k = 0; k < KH; k++) p[k] += __shfl_xor_sync(0xFFFFFFFFu, p[k], o);
    if (lane < KH) {
        float v = 0.f;
        #pragma unroll
        for (int k = 0; k < KH; k++) if (lane == k) v = p[k];
        g_er[w * KH + lane] = v;
    }
}

// ---------------- k1: mean over L, logits, exp, degree hist  (one warp / edge) ----------------
__global__ void k1(const float* __restrict__ edge_feat, const int* __restrict__ dst) {
    __shared__ float4 Vs[KH * 32];  // [k][d/4]
    int t = threadIdx.x;
    Vs[t] = ((const float4*)g_V)[t];
    __syncthreads();
    int w = (blockIdx.x * blockDim.x + t) >> 5;
    int lane = t & 31;
    if (w >= NE) return;
    const float4* ef = (const float4*)edge_feat + (size_t)w * 96;  // 3*128/4
    float4 x0 = ef[lane], x1 = ef[32 + lane], x2 = ef[64 + lane];
    const float inv3 = 1.f / 3.f;
    float4 m;
    m.x = (x0.x + x1.x + x2.x) * inv3;
    m.y = (x0.y + x1.y + x2.y) * inv3;
    m.z = (x0.z + x1.z + x2.z) * inv3;
    m.w = (x0.w + x1.w + x2.w) * inv3;
    ((float4*)g_mean)[(size_t)w * 32 + lane] = m;
    float p[KH];
    #pragma unroll
    for (int k = 0; k < KH; k++) {
        float4 v = Vs[k * 32 + lane];
        p[k] = m.x * v.x + m.y * v.y + m.z * v.z + m.w * v.w;
    }
    #pragma unroll
    for (int o = 16; o; o >>= 1)
        #pragma unroll
        for (int k = 0; k < KH; k++) p[k] += __shfl_xor_sync(0xFFFFFFFFu, p[k], o);
    int d = dst[w];
    if (lane == 0) atomicAdd(&g_deg[d], 1);
    if (lane < KH) {
        float el = 0.f;
        #pragma unroll
        for (int k = 0; k < KH; k++) if (lane == k) el = p[k];
        float lg = el + g_er[d * KH + lane];
        lg = (lg > 0.f) ? lg : 0.01f * lg;   // leaky relu
        g_ex[(size_t)w * KH + lane] = expf(lg);  // no max-sub: logits are small
    }
}

// ---------------- k_scan: exclusive prefix sum of degrees (1 block) ----------------
__global__ void k_scan() {
    const int CH = 20;  // 1024*20 = 20480 >= NN
    int t = threadIdx.x;
    int base = t * CH;
    int vals[CH];
    int sum = 0;
    #pragma unroll
    for (int i = 0; i < CH; i++) {
        int idx = base + i;
        int v = (idx < NN) ? g_deg[idx] : 0;
        vals[i] = sum;
        sum += v;
    }
    int lane = t & 31, wid = t >> 5;
    int inc = sum;
    #pragma unroll
    for (int o = 1; o < 32; o <<= 1) {
        int y = __shfl_up_sync(0xFFFFFFFFu, inc, o);
        if (lane >= o) inc += y;
    }
    __shared__ int wtot[32];
    if (lane == 31) wtot[wid] = inc;
    __syncthreads();
    if (wid == 0) {
        int v = wtot[lane];
        int i2 = v;
        #pragma unroll
        for (int o = 1; o < 32; o <<= 1) {
            int y = __shfl_up_sync(0xFFFFFFFFu, i2, o);
            if (lane >= o) i2 += y;
        }
        wtot[lane] = i2 - v;  // exclusive
    }
    __syncthreads();
    int gbase = wtot[wid] + (inc - sum);
    #pragma unroll
    for (int i = 0; i < CH; i++) {
        int idx = base + i;
        if (idx < NN) {
            int o = gbase + vals[i];
            g_off[idx] = o;
            g_cursor[idx] = o;
        }
    }
    if (t == 0) g_off[NN] = NE;
}

// ---------------- k_bucket: counting-sort edges by dst ----------------
__global__ void k_bucket(const int* __restrict__ dst) {
    int e = blockIdx.x * blockDim.x + threadIdx.x;
    if (e < NE) {
        int p = atomicAdd(&g_cursor[dst[e]], 1);
        g_order[p] = e;
    }
}

// ---------------- k3: per-node softmax-normalize + weighted aggregate of mean_edge ----------------
// one block (256 thr) per node; agg[k][d] kept in registers (4 floats/thread)
__global__ void k3() {
    int n = blockIdx.x;
    int t = threadIdx.x;
    int beg = g_off[n], end = g_off[n + 1];
    __shared__ float inv_s[KH];
    __shared__ float4 m_s[8 * 32];    // 8 edges x 128 floats
    __shared__ float a_s[8 * KH];
    if (t < KH) {
        float s = 0.f;
        for (int i = beg; i < end; i++) {
            int e = g_order[i];
            s += g_ex[(size_t)e * KH + t];
        }
        inv_s[t] = (s > 0.f) ? 1.f / s : 0.f;
    }
    __syncthreads();
    float4 acc = make_float4(0.f, 0.f, 0.f, 0.f);
    int k = t >> 5, ln = t & 31;
    for (int c = beg; c < end; c += 8) {
        int nc = min(8, end - c);
        if (k < nc) {
            int e = g_order[c + k];  // slot == k == t>>5
            m_s[k * 32 + ln] = ((const float4*)g_mean)[(size_t)e * 32 + ln];
            if (ln < KH) a_s[k * KH + ln] = g_ex[(size_t)e * KH + ln] * inv_s[ln];
        }
        __syncthreads();
        for (int s = 0; s < nc; s++) {
            float a = a_s[s * KH + k];
            float4 m = m_s[s * 32 + ln];
            acc.x += a * m.x;
            acc.y += a * m.y;
            acc.z += a * m.z;
            acc.w += a * m.w;
        }
        __syncthreads();
    }
    ((float4*)g_agg)[(size_t)n * 256 + t] = acc;  // flat = k*128+d = 4*t..4*t+3
}

// ---------------- k4: out[n,k,h] = agg[n,k,:] @ W_enc[:, k*64+h]  (tiled batched GEMM) ----------------
__global__ void k4(const float* __restrict__ W_enc, float* __restrict__ out) {
    const int NT = 64, DC = 32;
    int k = blockIdx.y;
    int n0 = blockIdx.x * NT;
    __shared__ float agg_s[NT][DC + 1];
    __shared__ float w_s[DC][HD + 1];
    int t = threadIdx.x;
    int tx = t & 15, ty = t >> 4;  // tx: h-group (4 h), ty: node-group (4 nodes)
    float acc[4][4] = {};
    for (int dc = 0; dc < DI; dc += DC) {
        #pragma unroll
        for (int i = 0; i < 8; i++) {
            int idx = t + i * 256;
            int r = idx >> 6, c = idx & 63;
            w_s[r][c] = W_enc[(dc + r) * (KH * HD) + k * HD + c];
        }
        #pragma unroll
        for (int i = 0; i < 8; i++) {
            int idx = t + i * 256;
            int nn = idx >> 5, d = idx & 31;
            int node = n0 + nn;
            agg_s[nn][d] = (node < NN) ? g_agg[(size_t)node * (KH * DI) + k * DI + dc + d] : 0.f;
        }
        __syncthreads();
        #pragma unroll
        for (int d = 0; d < DC; d++) {
            float av[4], wv[4];
            #pragma unroll
            for (int i = 0; i < 4; i++) av[i] = agg_s[ty * 4 + i][d];
            #pragma unroll
            for (int j = 0; j < 4; j++) wv[j] = w_s[d][tx * 4 + j];
            #pragma unroll
            for (int i = 0; i < 4; i++)
                #pragma unroll
                for (int j = 0; j < 4; j++) acc[i][j] += av[i] * wv[j];
        }
        __syncthreads();
    }
    #pragma unroll
    for (int i = 0; i < 4; i++) {
        int node = n0 + ty * 4 + i;
        if (node < NN) {
            #pragma unroll
            for (int j = 0; j < 4; j++)
                out[(size_t)node * (KH * HD) + k * HD + tx * 4 + j] = acc[i][j];
        }
    }
}

// ---------------- launch ----------------
extern "C" void kernel_launch(void* const* d_in, const int* in_sizes, int n_in,
                              void* d_out, int out_size) {
    const float* node_feat = (const float*)d_in[0];  // (N,128)
    const float* edge_feat = (const float*)d_in[1];  // (E,3,128)
    const float* W_enc     = (const float*)d_in[2];  // (128,512)
    const float* attn_l    = (const float*)d_in[3];  // (1,8,64)
    const float* W_r       = (const float*)d_in[4];  // (8,128)
    const int*   dst       = (const int*)d_in[5];    // (E,)
    float* out = (float*)d_out;                      // (N,8,64)

    k_zero<<<(NN + 255) / 256, 256>>>();
    k_v<<<1, 256>>>(W_enc, attn_l);
    k_er<<<(NN * 32 + 255) / 256, 256>>>(node_feat, W_r);
    k1<<<(NE * 32 + 255) / 256, 256>>>(edge_feat, dst);
    k_scan<<<1, 1024>>>();
    k_bucket<<<(NE + 255) / 256, 256>>>(dst);
    k3<<<NN, 256>>>();
    k4<<<dim3((NN + 63) / 64, KH), 256>>>(W_enc, out);
}

// round 2
// speedup vs baseline: 1.0489x; 1.0489x over previous
#include <cuda_runtime.h>
#include <cuda_bf16.h>
#include <math.h>

#define NN 20000      // nodes
#define NE 320000     // edges
#define DI 128        // d_in
#define KH 8          // heads
#define HD 64         // head dim

// ---------------- scratch (device globals: allocation-free) ----------------
__device__ __align__(16) float g_mean[(size_t)NE * DI];   // 163.84 MB
__device__ __align__(16) float g_ex[(size_t)NE * KH];     // 10.24 MB
__device__ __align__(16) float g_er[NN * KH];
__device__ __align__(16) float g_V[KH * DI];              // V[k*128+d]
__device__ __align__(16) float g_agg[(size_t)NN * KH * DI]; // 81.92 MB
__device__ __align__(16) float g_sum[NN * KH];            // softmax denominators
__device__ int g_deg[NN];
__device__ int g_off[NN + 1];
__device__ int g_cursor[NN];
__device__ int g_order[NE];

// ---------------- k_zero: clear degree histogram + softmax sums ----------------
__global__ void k_zero() {
    int i = blockIdx.x * blockDim.x + threadIdx.x;
    if (i < NN) g_deg[i] = 0;
    if (i < NN * KH) g_sum[i] = 0.f;
}

// ---------------- k_v: V[k][d] = sum_h W_enc[d, k*64+h] * attn_l[k,h] ----------------
__global__ void k_v(const float* __restrict__ W_enc, const float* __restrict__ attn_l) {
    __shared__ float al[KH * HD];
    int t = threadIdx.x;
    al[t] = attn_l[t];
    al[t + 256] = attn_l[t + 256];
    __syncthreads();
    for (int o = t; o < KH * DI; o += 256) {
        int k = o >> 7, d = o & 127;
        float s = 0.f;
        #pragma unroll 8
        for (int h = 0; h < HD; h++)
            s += W_enc[d * (KH * HD) + k * HD + h] * al[k * HD + h];
        g_V[o] = s;
    }
}

// ---------------- k_er: er[n,k] = node_feat[n,:] . W_r[k,:]  (one warp / node) ----------------
__global__ void k_er(const float* __restrict__ node_feat, const float* __restrict__ W_r) {
    __shared__ float4 Ws[KH * 32];  // [k][d/4]
    int t = threadIdx.x;
    Ws[t] = ((const float4*)W_r)[t];
    __syncthreads();
    int w = (blockIdx.x * blockDim.x + t) >> 5;
    int lane = t & 31;
    if (w >= NN) return;
    float4 x = ((const float4*)node_feat)[(size_t)w * 32 + lane];
    float p[KH];
    #pragma unroll
    for (int k = 0; k < KH; k++) {
        float4 v = Ws[k * 32 + lane];
        p[k] = x.x * v.x + x.y * v.y + x.z * v.z + x.w * v.w;
    }
    #pragma unroll
    for (int o = 16; o; o >>= 1)
        #pragma unroll
        for (int k = 0; k < KH; k++) p[k] += __shfl_xor_sync(0xFFFFFFFFu, p[k], o);
    if (lane < KH) {
        float v = 0.f;
        #pragma unroll
        for (int k = 0; k < KH; k++) if (lane == k) v = p[k];
        g_er[w * KH + lane] = v;
    }
}

// ---------------- k1: mean over L, logits, exp, degree hist, softmax-denominator atomics ----------------
__global__ void k1(const float* __restrict__ edge_feat, const int* __restrict__ dst) {
    __shared__ float4 Vs[KH * 32];  // [k][d/4]
    int t = threadIdx.x;
    Vs[t] = ((const float4*)g_V)[t];
    __syncthreads();
    int w = (blockIdx.x * blockDim.x + t) >> 5;
    int lane = t & 31;
    if (w >= NE) return;
    int d = dst[w];  // hoist: hide latency behind the feature loads
    const float4* ef = (const float4*)edge_feat + (size_t)w * 96;  // 3*128/4
    float4 x0 = ef[lane], x1 = ef[32 + lane], x2 = ef[64 + lane];
    const float inv3 = 1.f / 3.f;
    float4 m;
    m.x = (x0.x + x1.x + x2.x) * inv3;
    m.y = (x0.y + x1.y + x2.y) * inv3;
    m.z = (x0.z + x1.z + x2.z) * inv3;
    m.w = (x0.w + x1.w + x2.w) * inv3;
    __stcs(&((float4*)g_mean)[(size_t)w * 32 + lane], m);  // streaming store, no reuse soon
    float p[KH];
    #pragma unroll
    for (int k = 0; k < KH; k++) {
        float4 v = Vs[k * 32 + lane];
        p[k] = m.x * v.x + m.y * v.y + m.z * v.z + m.w * v.w;
    }
    #pragma unroll
    for (int o = 16; o; o >>= 1)
        #pragma unroll
        for (int k = 0; k < KH; k++) p[k] += __shfl_xor_sync(0xFFFFFFFFu, p[k], o);
    if (lane == 0) atomicAdd(&g_deg[d], 1);
    if (lane < KH) {
        float el = 0.f;
        #pragma unroll
        for (int k = 0; k < KH; k++) if (lane == k) el = p[k];
        float lg = el + g_er[d * KH + lane];
        lg = (lg > 0.f) ? lg : 0.01f * lg;          // leaky relu
        float ex = expf(lg);                        // no max-sub: logits are small
        g_ex[(size_t)w * KH + lane] = ex;
        atomicAdd(&g_sum[d * KH + lane], ex);       // softmax denominator
    }
}

// ---------------- k_scan: exclusive prefix sum of degrees (1 block) ----------------
__global__ void k_scan() {
    const int CH = 20;  // 1024*20 = 20480 >= NN
    int t = threadIdx.x;
    int base = t * CH;
    int vals[CH];
    int sum = 0;
    #pragma unroll
    for (int i = 0; i < CH; i++) {
        int idx = base + i;
        int v = (idx < NN) ? g_deg[idx] : 0;
        vals[i] = sum;
        sum += v;
    }
    int lane = t & 31, wid = t >> 5;
    int inc = sum;
    #pragma unroll
    for (int o = 1; o < 32; o <<= 1) {
        int y = __shfl_up_sync(0xFFFFFFFFu, inc, o);
        if (lane >= o) inc += y;
    }
    __shared__ int wtot[32];
    if (lane == 31) wtot[wid] = inc;
    __syncthreads();
    if (wid == 0) {
        int v = wtot[lane];
        int i2 = v;
        #pragma unroll
        for (int o = 1; o < 32; o <<= 1) {
            int y = __shfl_up_sync(0xFFFFFFFFu, i2, o);
            if (lane >= o) i2 += y;
        }
        wtot[lane] = i2 - v;  // exclusive
    }
    __syncthreads();
    int gbase = wtot[wid] + (inc - sum);
    #pragma unroll
    for (int i = 0; i < CH; i++) {
        int idx = base + i;
        if (idx < NN) {
            int o = gbase + vals[i];
            g_off[idx] = o;
            g_cursor[idx] = o;
        }
    }
    if (t == 0) g_off[NN] = NE;
}

// ---------------- k_bucket: counting-sort edges by dst ----------------
__global__ void k_bucket(const int* __restrict__ dst) {
    int e = blockIdx.x * blockDim.x + threadIdx.x;
    if (e < NE) {
        int p = atomicAdd(&g_cursor[dst[e]], 1);
        g_order[p] = e;
    }
}

// ---------------- k3: per-node weighted aggregate of mean_edge ----------------
// one block (256 thr) per node; agg[k][d] kept in registers (4 floats/thread)
// chunks of 16 edges: each warp gathers 2 independent rows (MLP 2)
__global__ void k3() {
    int n = blockIdx.x;
    int t = threadIdx.x;
    int beg = g_off[n], end = g_off[n + 1];
    __shared__ float inv_s[KH];
    __shared__ float4 m_s[16 * 32];    // 16 edges x 128 floats (8KB)
    __shared__ float a_s[16 * KH];
    if (t < KH) {
        float s = g_sum[n * KH + t];
        inv_s[t] = (s > 0.f) ? 1.f / s : 0.f;
    }
    __syncthreads();
    float4 acc = make_float4(0.f, 0.f, 0.f, 0.f);
    int k = t >> 5, ln = t & 31;
    for (int c = beg; c < end; c += 16) {
        int nc = min(16, end - c);
        #pragma unroll
        for (int s = k; s < 16; s += 8) {
            if (s < nc) {
                int e = __ldg(&g_order[c + s]);
                m_s[s * 32 + ln] = __ldcs(&((const float4*)g_mean)[(size_t)e * 32 + ln]);
                if (ln < KH) a_s[s * KH + ln] = g_ex[(size_t)e * KH + ln] * inv_s[ln];
            }
        }
        __syncthreads();
        for (int s = 0; s < nc; s++) {
            float a = a_s[s * KH + k];
            float4 m = m_s[s * 32 + ln];
            acc.x += a * m.x;
            acc.y += a * m.y;
            acc.z += a * m.z;
            acc.w += a * m.w;
        }
        __syncthreads();
    }
    ((float4*)g_agg)[(size_t)n * 256 + t] = acc;  // flat = k*128+d = 4*t..4*t+3
}

// ---------------- k4: out[n,k,h] = agg[n,k,:] @ W_enc[:, k*64+h]  (tiled batched GEMM) ----------------
__global__ void k4(const float* __restrict__ W_enc, float* __restrict__ out) {
    const int NT = 64, DC = 32;
    int k = blockIdx.y;
    int n0 = blockIdx.x * NT;
    __shared__ float agg_s[NT][DC + 1];
    __shared__ float w_s[DC][HD + 1];
    int t = threadIdx.x;
    int tx = t & 15, ty = t >> 4;  // tx: h-group (4 h), ty: node-group (4 nodes)
    float acc[4][4] = {};
    for (int dc = 0; dc < DI; dc += DC) {
        #pragma unroll
        for (int i = 0; i < 8; i++) {
            int idx = t + i * 256;
            int r = idx >> 6, c = idx & 63;
            w_s[r][c] = W_enc[(dc + r) * (KH * HD) + k * HD + c];
        }
        #pragma unroll
        for (int i = 0; i < 8; i++) {
            int idx = t + i * 256;
            int nn = idx >> 5, d = idx & 31;
            int node = n0 + nn;
            agg_s[nn][d] = (node < NN) ? g_agg[(size_t)node * (KH * DI) + k * DI + dc + d] : 0.f;
        }
        __syncthreads();
        #pragma unroll
        for (int d = 0; d < DC; d++) {
            float av[4], wv[4];
            #pragma unroll
            for (int i = 0; i < 4; i++) av[i] = agg_s[ty * 4 + i][d];
            #pragma unroll
            for (int j = 0; j < 4; j++) wv[j] = w_s[d][tx * 4 + j];
            #pragma unroll
            for (int i = 0; i < 4; i++)
                #pragma unroll
                for (int j = 0; j < 4; j++) acc[i][j] += av[i] * wv[j];
        }
        __syncthreads();
    }
    #pragma unroll
    for (int i = 0; i < 4; i++) {
        int node = n0 + ty * 4 + i;
        if (node < NN) {
            #pragma unroll
            for (int j = 0; j < 4; j++)
                out[(size_t)node * (KH * HD) + k * HD + tx * 4 + j] = acc[i][j];
        }
    }
}

// ---------------- launch ----------------
extern "C" void kernel_launch(void* const* d_in, const int* in_sizes, int n_in,
                              void* d_out, int out_size) {
    const float* node_feat = (const float*)d_in[0];  // (N,128)
    const float* edge_feat = (const float*)d_in[1];  // (E,3,128)
    const float* W_enc     = (const float*)d_in[2];  // (128,512)
    const float* attn_l    = (const float*)d_in[3];  // (1,8,64)
    const float* W_r       = (const float*)d_in[4];  // (8,128)
    const int*   dst       = (const int*)d_in[5];    // (E,)
    float* out = (float*)d_out;                      // (N,8,64)

    k_zero<<<(NN * KH + 255) / 256, 256>>>();
    k_v<<<1, 256>>>(W_enc, attn_l);
    k_er<<<(NN * 32 + 255) / 256, 256>>>(node_feat, W_r);
    k1<<<(NE * 32 + 255) / 256, 256>>>(edge_feat, dst);
    k_scan<<<1, 1024>>>();
    k_bucket<<<(NE + 255) / 256, 256>>>(dst);
    k3<<<NN, 256>>>();
    k4<<<dim3((NN + 63) / 64, KH), 256>>>(W_enc, out);
}

// round 5
// speedup vs baseline: 1.2549x; 1.1964x over previous
#include <cuda_runtime.h>
#include <cuda_bf16.h>
#include <cstdint>
#include <math.h>

#define NN 20000      // nodes
#define NE 320000     // edges
#define DI 128        // d_in
#define KH 8          // heads
#define HD 64         // head dim

typedef unsigned int u32;

// ---------------- scratch (device globals: allocation-free) ----------------
__device__ __align__(16) float g_mean[(size_t)NE * DI];   // 163.84 MB
__device__ __align__(16) float g_ex[(size_t)NE * KH];     // 10.24 MB
__device__ __align__(16) float g_er[NN * KH];
__device__ __align__(16) float g_V[KH * DI];              // V[k*128+d]
__device__ __align__(16) float g_agg[(size_t)NN * KH * DI]; // 81.92 MB
__device__ __align__(16) float g_sum[NN * KH];            // softmax denominators
__device__ int g_deg[NN];
__device__ int g_off[NN + 1];
__device__ int g_cursor[NN];
__device__ int g_order[NE];

// ---------------- k_zero ----------------
__global__ void k_zero() {
    int i = blockIdx.x * blockDim.x + threadIdx.x;
    if (i < NN) g_deg[i] = 0;
    if (i < NN * KH) g_sum[i] = 0.f;
}

// ---------------- k_v: V[k][d] = sum_h W_enc[d, k*64+h] * attn_l[k,h] ----------------
__global__ void k_v(const float* __restrict__ W_enc, const float* __restrict__ attn_l) {
    __shared__ float al[KH * HD];
    int t = threadIdx.x;
    al[t] = attn_l[t];
    al[t + 256] = attn_l[t + 256];
    __syncthreads();
    for (int o = t; o < KH * DI; o += 256) {
        int k = o >> 7, d = o & 127;
        float s = 0.f;
        #pragma unroll 8
        for (int h = 0; h < HD; h++)
            s += W_enc[d * (KH * HD) + k * HD + h] * al[k * HD + h];
        g_V[o] = s;
    }
}

// ---------------- k_er: er[n,k] = node_feat[n,:] . W_r[k,:]  (one warp / node) ----------------
__global__ void k_er(const float* __restrict__ node_feat, const float* __restrict__ W_r) {
    __shared__ float4 Ws[KH * 32];
    int t = threadIdx.x;
    Ws[t] = ((const float4*)W_r)[t];
    __syncthreads();
    int w = (blockIdx.x * blockDim.x + t) >> 5;
    int lane = t & 31;
    if (w >= NN) return;
    float4 x = ((const float4*)node_feat)[(size_t)w * 32 + lane];
    float p[KH];
    #pragma unroll
    for (int k = 0; k < KH; k++) {
        float4 v = Ws[k * 32 + lane];
        p[k] = x.x * v.x + x.y * v.y + x.z * v.z + x.w * v.w;
    }
    #pragma unroll
    for (int o = 16; o; o >>= 1)
        #pragma unroll
        for (int k = 0; k < KH; k++) p[k] += __shfl_xor_sync(0xFFFFFFFFu, p[k], o);
    if (lane < KH) {
        float v = 0.f;
        #pragma unroll
        for (int k = 0; k < KH; k++) if (lane == k) v = p[k];
        g_er[w * KH + lane] = v;
    }
}

// ---------------- k1: mean over L, logits, exp, hist, softmax denominators ----------------
__global__ void k1(const float* __restrict__ edge_feat, const int* __restrict__ dst) {
    __shared__ float4 Vs[KH * 32];
    int t = threadIdx.x;
    Vs[t] = ((const float4*)g_V)[t];
    __syncthreads();
    int w = (blockIdx.x * blockDim.x + t) >> 5;
    int lane = t & 31;
    if (w >= NE) return;
    int d = dst[w];
    const float4* ef = (const float4*)edge_feat + (size_t)w * 96;
    float4 x0 = ef[lane], x1 = ef[32 + lane], x2 = ef[64 + lane];
    const float inv3 = 1.f / 3.f;
    float4 m;
    m.x = (x0.x + x1.x + x2.x) * inv3;
    m.y = (x0.y + x1.y + x2.y) * inv3;
    m.z = (x0.z + x1.z + x2.z) * inv3;
    m.w = (x0.w + x1.w + x2.w) * inv3;
    __stcs(&((float4*)g_mean)[(size_t)w * 32 + lane], m);
    float p[KH];
    #pragma unroll
    for (int k = 0; k < KH; k++) {
        float4 v = Vs[k * 32 + lane];
        p[k] = m.x * v.x + m.y * v.y + m.z * v.z + m.w * v.w;
    }
    #pragma unroll
    for (int o = 16; o; o >>= 1)
        #pragma unroll
        for (int k = 0; k < KH; k++) p[k] += __shfl_xor_sync(0xFFFFFFFFu, p[k], o);
    if (lane == 0) atomicAdd(&g_deg[d], 1);
    if (lane < KH) {
        float el = 0.f;
        #pragma unroll
        for (int k = 0; k < KH; k++) if (lane == k) el = p[k];
        float lg = el + g_er[d * KH + lane];
        lg = (lg > 0.f) ? lg : 0.01f * lg;
        float ex = expf(lg);
        g_ex[(size_t)w * KH + lane] = ex;
        atomicAdd(&g_sum[d * KH + lane], ex);
    }
}

// ---------------- k_scan: exclusive prefix sum of degrees (1 block) ----------------
__global__ void k_scan() {
    const int CH = 20;
    int t = threadIdx.x;
    int base = t * CH;
    int vals[CH];
    int sum = 0;
    #pragma unroll
    for (int i = 0; i < CH; i++) {
        int idx = base + i;
        int v = (idx < NN) ? g_deg[idx] : 0;
        vals[i] = sum;
        sum += v;
    }
    int lane = t & 31, wid = t >> 5;
    int inc = sum;
    #pragma unroll
    for (int o = 1; o < 32; o <<= 1) {
        int y = __shfl_up_sync(0xFFFFFFFFu, inc, o);
        if (lane >= o) inc += y;
    }
    __shared__ int wtot[32];
    if (lane == 31) wtot[wid] = inc;
    __syncthreads();
    if (wid == 0) {
        int v = wtot[lane];
        int i2 = v;
        #pragma unroll
        for (int o = 1; o < 32; o <<= 1) {
            int y = __shfl_up_sync(0xFFFFFFFFu, i2, o);
            if (lane >= o) i2 += y;
        }
        wtot[lane] = i2 - v;
    }
    __syncthreads();
    int gbase = wtot[wid] + (inc - sum);
    #pragma unroll
    for (int i = 0; i < CH; i++) {
        int idx = base + i;
        if (idx < NN) {
            int o = gbase + vals[i];
            g_off[idx] = o;
            g_cursor[idx] = o;
        }
    }
    if (t == 0) g_off[NN] = NE;
}

// ---------------- k_bucket: counting-sort edges by dst ----------------
__global__ void k_bucket(const int* __restrict__ dst) {
    int e = blockIdx.x * blockDim.x + threadIdx.x;
    if (e < NE) {
        int p = atomicAdd(&g_cursor[dst[e]], 1);
        g_order[p] = e;
    }
}

// ---------------- k3: per-node weighted aggregate of mean_edge ----------------
__global__ void k3() {
    int n = blockIdx.x;
    int t = threadIdx.x;
    int beg = g_off[n], end = g_off[n + 1];
    __shared__ float inv_s[KH];
    __shared__ float4 m_s[16 * 32];
    __shared__ float a_s[16 * KH];
    if (t < KH) {
        float s = g_sum[n * KH + t];
        inv_s[t] = (s > 0.f) ? 1.f / s : 0.f;
    }
    __syncthreads();
    float4 acc = make_float4(0.f, 0.f, 0.f, 0.f);
    int k = t >> 5, ln = t & 31;
    for (int c = beg; c < end; c += 16) {
        int nc = min(16, end - c);
        #pragma unroll
        for (int s = k; s < 16; s += 8) {
            if (s < nc) {
                int e = __ldg(&g_order[c + s]);
                m_s[s * 32 + ln] = __ldcs(&((const float4*)g_mean)[(size_t)e * 32 + ln]);
                if (ln < KH) a_s[s * KH + ln] = g_ex[(size_t)e * KH + ln] * inv_s[ln];
            }
        }
        __syncthreads();
        for (int s = 0; s < nc; s++) {
            float a = a_s[s * KH + k];
            float4 m = m_s[s * 32 + ln];
            acc.x += a * m.x;
            acc.y += a * m.y;
            acc.z += a * m.z;
            acc.w += a * m.w;
        }
        __syncthreads();
    }
    ((float4*)g_agg)[(size_t)n * 256 + t] = acc;
}

// ---------------- k4: tensor-core batched GEMM with split-bf16 (3-pass) ----------------
// out[n, k*64+h] = sum_d agg[n,k,d] * W_enc[d, k*64+h]
// grid = (ceil(NN/128), 8); block = 256 (8 warps); warp w owns rows w*16..w*16+15.
// K processed in 2 chunks of 64. smem holds bf16 hi/lo of A tile and B^T tile,
// XOR-swizzled (pair index p ^ ((row&7)<<2)) for conflict-free fragment loads.

__device__ __forceinline__ void split2(float a, float b, u32& hi, u32& lo) {
    __nv_bfloat16 ha = __float2bfloat16(a);
    __nv_bfloat16 hb = __float2bfloat16(b);
    __nv_bfloat16 la = __float2bfloat16(a - __bfloat162float(ha));
    __nv_bfloat16 lb = __float2bfloat16(b - __bfloat162float(hb));
    hi = (u32)__bfloat16_as_ushort(ha) | ((u32)__bfloat16_as_ushort(hb) << 16);
    lo = (u32)__bfloat16_as_ushort(la) | ((u32)__bfloat16_as_ushort(lb) << 16);
}
#define SWZ(p, r) ((p) ^ (((r) & 7) << 2))

#define MMA_BF16(dd, aa, b0, b1) \
    asm volatile("mma.sync.aligned.m16n8k16.row.col.f32.bf16.bf16.f32 " \
                 "{%0,%1,%2,%3},{%4,%5,%6,%7},{%8,%9},{%0,%1,%2,%3};\n" \
                 : "+f"(dd[0]), "+f"(dd[1]), "+f"(dd[2]), "+f"(dd[3]) \
                 : "r"(aa[0]), "r"(aa[1]), "r"(aa[2]), "r"(aa[3]), "r"(b0), "r"(b1))

__global__ __launch_bounds__(256, 4) void k4(const float* __restrict__ W_enc,
                                             float* __restrict__ out) {
    __shared__ u32 sAh[128][32];  // [node][pair]  16KB
    __shared__ u32 sAl[128][32];  // 16KB
    __shared__ u32 sBh[64][32];   // [h][pair]     8KB
    __shared__ u32 sBl[64][32];   // 8KB
    const int k = blockIdx.y;
    const int m0 = blockIdx.x * 128;
    const int kcol = k * HD;
    const int t = threadIdx.x;
    const int w = t >> 5, lane = t & 31;
    const int g = lane >> 2, q = lane & 3;
    const int mrow = w * 16;

    float acc[8][4];
    #pragma unroll
    for (int nt = 0; nt < 8; nt++)
        #pragma unroll
        for (int i = 0; i < 4; i++) acc[nt][i] = 0.f;

    for (int ch = 0; ch < 2; ch++) {
        int d0 = ch * 64;
        // ---- fill A tile: 128 nodes x 64 d (float4 loads, split to bf16 hi/lo) ----
        #pragma unroll
        for (int i = 0; i < 8; i++) {
            int idx = i * 256 + t;           // 2048 float4s
            int node = idx >> 4, f4i = idx & 15;
            float4 v = make_float4(0.f, 0.f, 0.f, 0.f);
            if (m0 + node < NN)
                v = *(const float4*)&g_agg[(size_t)(m0 + node) * (KH * DI) + k * DI + d0 + f4i * 4];
            u32 h0, l0, h1, l1;
            split2(v.x, v.y, h0, l0);
            split2(v.z, v.w, h1, l1);
            int p0 = f4i * 2, p1 = f4i * 2 + 1;
            sAh[node][SWZ(p0, node)] = h0;
            sAl[node][SWZ(p0, node)] = l0;
            sAh[node][SWZ(p1, node)] = h1;
            sAl[node][SWZ(p1, node)] = l1;
        }
        // ---- fill B^T tile: 64 h x 32 pairs (pairs along d) ----
        #pragma unroll
        for (int i = 0; i < 8; i++) {
            int idx = i * 256 + t;           // 2048 (p,h) items
            int p = idx >> 6, h = idx & 63;
            int d = d0 + 2 * p;
            float w0 = W_enc[(size_t)d * (KH * HD) + kcol + h];
            float w1 = W_enc[(size_t)(d + 1) * (KH * HD) + kcol + h];
            u32 hi, lo;
            split2(w0, w1, hi, lo);
            sBh[h][SWZ(p, h)] = hi;
            sBl[h][SWZ(p, h)] = lo;
        }
        __syncthreads();
        // ---- MMA mainloop: 4 k-steps of 16 ----
        #pragma unroll
        for (int ks = 0; ks < 4; ks++) {
            int pb = ks * 8;
            int r0 = mrow + g, r1 = mrow + g + 8;
            u32 ah[4], al[4];
            ah[0] = sAh[r0][SWZ(pb + q, r0)];
            ah[1] = sAh[r1][SWZ(pb + q, r1)];
            ah[2] = sAh[r0][SWZ(pb + q + 4, r0)];
            ah[3] = sAh[r1][SWZ(pb + q + 4, r1)];
            al[0] = sAl[r0][SWZ(pb + q, r0)];
            al[1] = sAl[r1][SWZ(pb + q, r1)];
            al[2] = sAl[r0][SWZ(pb + q + 4, r0)];
            al[3] = sAl[r1][SWZ(pb + q + 4, r1)];
            #pragma unroll
            for (int nt = 0; nt < 8; nt++) {
                int nr = nt * 8 + g;
                u32 bh0 = sBh[nr][SWZ(pb + q, nr)];
                u32 bh1 = sBh[nr][SWZ(pb + q + 4, nr)];
                u32 bl0 = sBl[nr][SWZ(pb + q, nr)];
                u32 bl1 = sBl[nr][SWZ(pb + q + 4, nr)];
                MMA_BF16(acc[nt], ah, bh0, bh1);   // hi*hi
                MMA_BF16(acc[nt], ah, bl0, bl1);   // hi*lo
                MMA_BF16(acc[nt], al, bh0, bh1);   // lo*hi
            }
        }
        __syncthreads();
    }
    // ---- store: c0=(g,2q) c1=(g,2q+1) c2=(g+8,2q) c3=(g+8,2q+1) ----
    int row0 = m0 + mrow + g;
    int row1 = row0 + 8;
    #pragma unroll
    for (int nt = 0; nt < 8; nt++) {
        int col = kcol + nt * 8 + 2 * q;
        if (row0 < NN) {
            out[(size_t)row0 * (KH * HD) + col]     = acc[nt][0];
            out[(size_t)row0 * (KH * HD) + col + 1] = acc[nt][1];
        }
        if (row1 < NN) {
            out[(size_t)row1 * (KH * HD) + col]     = acc[nt][2];
            out[(size_t)row1 * (KH * HD) + col + 1] = acc[nt][3];
        }
    }
}

// ---------------- launch ----------------
extern "C" void kernel_launch(void* const* d_in, const int* in_sizes, int n_in,
                              void* d_out, int out_size) {
    const float* node_feat = (const float*)d_in[0];  // (N,128)
    const float* edge_feat = (const float*)d_in[1];  // (E,3,128)
    const float* W_enc     = (const float*)d_in[2];  // (128,512)
    const float* attn_l    = (const float*)d_in[3];  // (1,8,64)
    const float* W_r       = (const float*)d_in[4];  // (8,128)
    const int*   dst       = (const int*)d_in[5];    // (E,)
    float* out = (float*)d_out;                      // (N,8,64)

    k_zero<<<(NN * KH + 255) / 256, 256>>>();
    k_v<<<1, 256>>>(W_enc, attn_l);
    k_er<<<(NN * 32 + 255) / 256, 256>>>(node_feat, W_r);
    k1<<<(NE * 32 + 255) / 256, 256>>>(edge_feat, dst);
    k_scan<<<1, 1024>>>();
    k_bucket<<<(NE + 255) / 256, 256>>>(dst);
    k3<<<NN, 256>>>();
    k4<<<dim3((NN + 127) / 128, KH), 256>>>(W_enc, out);
}